// round 11
// baseline (speedup 1.0000x reference)
#include <cuda_runtime.h>
#include <cuda_fp16.h>
#include <math_constants.h>
#include <cstdint>

#define Bb 64
#define Ss 2048
#define Hh 1024
#define Aa 512

// ---------------- device scratch (no allocation allowed) --------------------
__device__ float g_C[Bb * Aa];
__device__ float g_sc0[Bb * Ss];
__device__ float g_sc1[Bb * Ss];
__device__ float g_opart[Bb * 16 * Hh];
__device__ __half g_W16[Aa * Hh];

// ---------------- helpers ---------------------------------------------------
__device__ __forceinline__ uint32_t smem_u32(const void* p) {
    uint32_t a;
    asm("{ .reg .u64 t; cvta.to.shared.u64 t, %1; cvt.u32.u64 %0, t; }" : "=r"(a) : "l"(p));
    return a;
}
__device__ __forceinline__ void cp_async16(uint32_t dst, const void* src) {
    asm volatile("cp.async.cg.shared.global [%0], [%1], 16;" :: "r"(dst), "l"(src) : "memory");
}
__device__ __forceinline__ void cp_commit() {
    asm volatile("cp.async.commit_group;" ::: "memory");
}
__device__ __forceinline__ void ldmx4(uint32_t& r0, uint32_t& r1, uint32_t& r2, uint32_t& r3,
                                      uint32_t addr) {
    asm volatile("ldmatrix.sync.aligned.m8n8.x4.shared.b16 {%0,%1,%2,%3}, [%4];"
                 : "=r"(r0), "=r"(r1), "=r"(r2), "=r"(r3) : "r"(addr));
}
__device__ __forceinline__ void mma_f16(float* d, const uint32_t* a, const uint32_t* b) {
    asm volatile(
        "mma.sync.aligned.m16n8k16.row.col.f32.f16.f16.f32 "
        "{%0,%1,%2,%3}, {%4,%5,%6,%7}, {%8,%9}, {%0,%1,%2,%3};"
        : "+f"(d[0]), "+f"(d[1]), "+f"(d[2]), "+f"(d[3])
        : "r"(a[0]), "r"(a[1]), "r"(a[2]), "r"(a[3]), "r"(b[0]), "r"(b[1]));
}
__device__ __forceinline__ uint32_t pack_h2(float a, float b) {
    __half2 h = __float22half2_rn(make_float2(a, b));
    return *(uint32_t*)&h;
}

// smem: 2 stages of [X sub0 5120 | X sub1 5120 | W sub0 20480 | W sub1 20480]
// (80B rows; CTA tile 64x256, BK=64 as two 32-wide sub-chunks)
#define STG_SZ   51200
#define OFF_XB   5120
#define OFF_WA   10240
#define OFF_WB   30720
#define OFF_SCP  102400           // 256 floats
#define OFF_CS   103424           // 256 floats
#define OFF_VS   104448           // 256 floats
#define SMEM_SZ  105472

// ---------------------------------------------------------------------------
// prep_w: round Wh (fp32 [512][1024]) to fp16, row-major single plane.
// ---------------------------------------------------------------------------
__global__ void prep_w(const float* __restrict__ Wh) {
    int a = blockIdx.x;
    int t = threadIdx.x;
    float4 v = *(const float4*)(Wh + (size_t)a * 1024 + t * 4);
    uint2 w;
    w.x = pack_h2(v.x, v.y);
    w.y = pack_h2(v.z, v.w);
    *(uint2*)(g_W16 + (size_t)a * 1024 + t * 4) = w;
}

// ---------------------------------------------------------------------------
// ctx: C[b,a] = Wh_b[a] + x0@W0[a] + x1@W1[a] + x2@W2[a]
// ---------------------------------------------------------------------------
__global__ void ctx_kernel(const float* __restrict__ x0,
                           const float* __restrict__ x1,
                           const float* __restrict__ x2,
                           const float* __restrict__ W0,
                           const float* __restrict__ W1,
                           const float* __restrict__ W2,
                           const float* __restrict__ Whb) {
    __shared__ float xs[2048];
    int b = blockIdx.x;
    int t = threadIdx.x;
    xs[t]        = x0[b * 1024 + t];
    xs[t + 512]  = x0[b * 1024 + t + 512];
    xs[1024 + t] = x1[b * 512 + t];
    xs[1536 + t] = x2[b * 512 + t];
    __syncthreads();
    int a = t;
    float acc = Whb[a];
    const float4* w0 = (const float4*)(W0 + (size_t)a * 1024);
    const float4* xv = (const float4*)xs;
#pragma unroll 8
    for (int i = 0; i < 256; i++) {
        float4 w = w0[i]; float4 x = xv[i];
        acc += w.x * x.x + w.y * x.y + w.z * x.z + w.w * x.w;
    }
    const float4* w1 = (const float4*)(W1 + (size_t)a * 512);
    const float4* x1v = (const float4*)(xs + 1024);
#pragma unroll 8
    for (int i = 0; i < 128; i++) {
        float4 w = w1[i]; float4 x = x1v[i];
        acc += w.x * x.x + w.y * x.y + w.z * x.z + w.w * x.w;
    }
    const float4* w2 = (const float4*)(W2 + (size_t)a * 512);
    const float4* x2v = (const float4*)(xs + 1536);
#pragma unroll 8
    for (int i = 0; i < 128; i++) {
        float4 w = w2[i]; float4 x = x2v[i];
        acc += w.x * x.x + w.y * x.y + w.z * x.z + w.w * x.w;
    }
    g_C[b * Aa + a] = acc;
}

// ---------------------------------------------------------------------------
// scores_mma: fused scores, fp16 single-pass, CTA tile 64x256, BK=64,
// 256 threads = 8 warps (2x4), warp tile 32x64. 2 CTAs/SM for overlap.
// grid (32 st, 2 ah, 64 b).
// ---------------------------------------------------------------------------
__global__ void __launch_bounds__(256, 2)
scores_mma(const float* __restrict__ X,
           const float* __restrict__ V,
           const int* __restrict__ lengths) {
    extern __shared__ char smem[];
    int st = blockIdx.x, ah = blockIdx.y, b = blockIdx.z;
    int len = lengths[b];
    int s0 = st * 64;
    if (s0 >= len) return;

    int tid = threadIdx.x;
    int wid = tid >> 5;
    int lane = tid & 31;
    int wm = wid >> 2;       // 0..1 : rows wm*32
    int wn = wid & 3;        // 0..3 : cols wn*64

    float* cs = (float*)(smem + OFF_CS);
    float* vs = (float*)(smem + OFF_VS);
    cs[tid] = g_C[b * Aa + ah * 256 + tid];
    vs[tid] = V[ah * 256 + tid];

    uint32_t sbase = smem_u32(smem);

    // ---- X mapping: per sub-chunk 512 slots of 4 fp32; 2 slots/thread
    int xrow0 = (tid * 2) >> 3;
    int xq0   = (tid * 2) & 7;
    int xrow1 = (tid * 2 + 1) >> 3;
    int xq1   = (tid * 2 + 1) & 7;
    const float* Xb = X + ((size_t)b * Ss + s0) * Hh;

    // ---- W cp.async mapping: per sub-chunk 1024 ops of 16B; 4 ops/thread
    const __half* wsrc[4];
    uint32_t wdst[4];
#pragma unroll
    for (int i = 0; i < 4; i++) {
        int l = tid * 4 + i;
        int row = l >> 2, ch = l & 3;
        wsrc[i] = g_W16 + ((size_t)(ah * 256 + row)) * Hh + ch * 8;
        wdst[i] = OFF_WA + row * 80 + ch * 16;
    }

    auto issueW = [&](int ck, uint32_t stage_u32) {
        int k0 = ck * 64;
#pragma unroll
        for (int i = 0; i < 4; i++) {
            cp_async16(stage_u32 + wdst[i], wsrc[i] + k0);
            cp_async16(stage_u32 + wdst[i] + (OFF_WB - OFF_WA), wsrc[i] + k0 + 32);
        }
        cp_commit();
    };
    auto loadX = [&](int ck, float4* v) {
        int k0 = ck * 64;
        v[0] = *(const float4*)(Xb + (size_t)xrow0 * Hh + k0 + xq0 * 4);
        v[1] = *(const float4*)(Xb + (size_t)xrow1 * Hh + k0 + xq1 * 4);
        v[2] = *(const float4*)(Xb + (size_t)xrow0 * Hh + k0 + 32 + xq0 * 4);
        v[3] = *(const float4*)(Xb + (size_t)xrow1 * Hh + k0 + 32 + xq1 * 4);
    };
    auto storeX = [&](char* sp, const float4* v) {
        uint2 p;
        p.x = pack_h2(v[0].x, v[0].y); p.y = pack_h2(v[0].z, v[0].w);
        *(uint2*)(sp + xrow0 * 80 + xq0 * 8) = p;
        p.x = pack_h2(v[1].x, v[1].y); p.y = pack_h2(v[1].z, v[1].w);
        *(uint2*)(sp + xrow1 * 80 + xq1 * 8) = p;
        p.x = pack_h2(v[2].x, v[2].y); p.y = pack_h2(v[2].z, v[2].w);
        *(uint2*)(sp + OFF_XB + xrow0 * 80 + xq0 * 8) = p;
        p.x = pack_h2(v[3].x, v[3].y); p.y = pack_h2(v[3].z, v[3].w);
        *(uint2*)(sp + OFF_XB + xrow1 * 80 + xq1 * 8) = p;
    };

    // ---- ldmatrix lane geometry (80B rows)
    uint32_t t8 = lane >> 3;
    uint32_t l7 = lane & 7;
    uint32_t arow[2], nrow[4];
#pragma unroll
    for (int i = 0; i < 2; i++)
        arow[i] = (wm * 32 + i * 16 + ((t8 & 1) << 3) + l7) * 80;
#pragma unroll
    for (int g = 0; g < 4; g++)
        nrow[g] = (wn * 64 + (g * 2 + (t8 >> 1)) * 8 + l7) * 80;
    uint32_t ka = (t8 >> 1) << 4;
    uint32_t kb_b = (t8 & 1) << 4;

    float acc[2][8][4];
#pragma unroll
    for (int i = 0; i < 2; i++)
#pragma unroll
        for (int j = 0; j < 8; j++)
#pragma unroll
            for (int r = 0; r < 4; r++) acc[i][j][r] = 0.f;

    // ---- prologue: fill stages 0,1
    {
        float4 v[4];
        issueW(0, sbase);
        loadX(0, v);
        storeX(smem, v);
        issueW(1, sbase + STG_SZ);
        loadX(1, v);
        storeX(smem + STG_SZ, v);
    }

    // ---- main loop: 16 k-iters of BK=64, 2 barriers each
    float4 pv[4];
#pragma unroll 1
    for (int ck = 0; ck < 16; ck++) {
        if (ck == 15) asm volatile("cp.async.wait_group 0;" ::: "memory");
        else          asm volatile("cp.async.wait_group 1;" ::: "memory");
        __syncthreads();

        if (ck + 2 <= 15) loadX(ck + 2, pv);

        uint32_t sb = sbase + (uint32_t)(ck & 1) * STG_SZ;
#pragma unroll
        for (int h = 0; h < 2; h++) {
            uint32_t Ab = sb + (uint32_t)h * OFF_XB;
            uint32_t Bbs = sb + OFF_WA + (uint32_t)h * (OFF_WB - OFF_WA);
#pragma unroll
            for (int kf = 0; kf < 2; kf++) {
                uint32_t k16 = kf * 32;
                uint32_t bf[8][2];
#pragma unroll
                for (int g = 0; g < 4; g++) {
                    uint32_t r0, r1, r2, r3;
                    ldmx4(r0, r1, r2, r3, Bbs + nrow[g] + k16 + kb_b);
                    bf[2 * g][0] = r0; bf[2 * g][1] = r1;
                    bf[2 * g + 1][0] = r2; bf[2 * g + 1][1] = r3;
                }
                uint32_t a16[2][4];
#pragma unroll
                for (int i = 0; i < 2; i++)
                    ldmx4(a16[i][0], a16[i][1], a16[i][2], a16[i][3], Ab + arow[i] + k16 + ka);
#pragma unroll
                for (int i = 0; i < 2; i++)
#pragma unroll
                    for (int j = 0; j < 8; j++)
                        mma_f16(acc[i][j], a16[i], bf[j]);
            }
        }
        __syncthreads();

        if (ck + 2 <= 15) {
            storeX(smem + (ck & 1) * STG_SZ, pv);
            issueW(ck + 2, sbase + (uint32_t)(ck & 1) * STG_SZ);
        }
    }

    // ---- epilogue: relu(acc + C) dot V, reduce to per-row scores
    float rs[4] = {0.f, 0.f, 0.f, 0.f};
#pragma unroll
    for (int i = 0; i < 2; i++) {
#pragma unroll
        for (int j = 0; j < 8; j++) {
            int c = wn * 64 + j * 8 + (lane & 3) * 2;
            float v0 = vs[c], v1 = vs[c + 1];
            float c0 = cs[c], c1 = cs[c + 1];
            rs[i * 2 + 0] += fmaxf(acc[i][j][0] + c0, 0.f) * v0
                           + fmaxf(acc[i][j][1] + c1, 0.f) * v1;
            rs[i * 2 + 1] += fmaxf(acc[i][j][2] + c0, 0.f) * v0
                           + fmaxf(acc[i][j][3] + c1, 0.f) * v1;
        }
    }
#pragma unroll
    for (int r = 0; r < 4; r++) {
        rs[r] += __shfl_xor_sync(0xffffffffu, rs[r], 1);
        rs[r] += __shfl_xor_sync(0xffffffffu, rs[r], 2);
    }
    float* scp = (float*)(smem + OFF_SCP);
    if ((lane & 3) == 0) {
        int row = wm * 32 + (lane >> 2);
        scp[wn * 64 + row + 0]  = rs[0];
        scp[wn * 64 + row + 8]  = rs[1];
        scp[wn * 64 + row + 16] = rs[2];
        scp[wn * 64 + row + 24] = rs[3];
    }
    __syncthreads();
    if (tid < 64) {
        float v = scp[tid] + scp[64 + tid] + scp[128 + tid] + scp[192 + tid];
        (ah ? g_sc1 : g_sc0)[b * Ss + s0 + tid] = v;
    }
}

// ---------------------------------------------------------------------------
// softmax over s<len of (g_sc0+g_sc1); prob -> out[B*H ...]
// ---------------------------------------------------------------------------
__global__ void softmax_kernel(const int* __restrict__ lengths, float* __restrict__ out) {
    int b = blockIdx.x;
    int len = lengths[b];
    int tid = threadIdx.x;
    const float* a0 = g_sc0 + b * Ss;
    const float* a1 = g_sc1 + b * Ss;
    float* prob = out + Bb * Hh + (size_t)b * Ss;

    __shared__ float red[8];
    __shared__ float s_m, s_sum;

    float m = -CUDART_INF_F;
    for (int s = tid; s < len; s += 256) m = fmaxf(m, a0[s] + a1[s]);
#pragma unroll
    for (int o = 16; o > 0; o >>= 1) m = fmaxf(m, __shfl_xor_sync(~0u, m, o));
    if ((tid & 31) == 0) red[tid >> 5] = m;
    __syncthreads();
    if (tid == 0) {
        float mm = red[0];
#pragma unroll
        for (int i = 1; i < 8; i++) mm = fmaxf(mm, red[i]);
        s_m = mm;
    }
    __syncthreads();
    m = s_m;

    float sum = 0.f;
    for (int s = tid; s < len; s += 256) sum += expf(a0[s] + a1[s] - m);
#pragma unroll
    for (int o = 16; o > 0; o >>= 1) sum += __shfl_xor_sync(~0u, sum, o);
    if ((tid & 31) == 0) red[tid >> 5] = sum;
    __syncthreads();
    if (tid == 0) {
        float ss = 0.f;
#pragma unroll
        for (int i = 0; i < 8; i++) ss += red[i];
        s_sum = ss;
    }
    __syncthreads();
    float inv = 1.f / s_sum;

    for (int s = tid; s < Ss; s += 256)
        prob[s] = (s < len) ? expf(a0[s] + a1[s] - m) * inv : 0.f;
}

// ---------------------------------------------------------------------------
// output pass, two-phase
// ---------------------------------------------------------------------------
__global__ void output_partial(const float* __restrict__ X,
                               const int* __restrict__ lengths,
                               const float* __restrict__ out) {
    int sc = blockIdx.x, b = blockIdx.y;
    int len = lengths[b];
    int s0 = sc * 128;
    if (s0 >= len) return;
    int n = min(128, len - s0);
    int tid = threadIdx.x;
    const float4* Xb = (const float4*)X + ((size_t)(b * Ss + s0)) * 256 + tid;
    const float* prob = out + Bb * Hh + (size_t)b * Ss + s0;
    float4 acc = make_float4(0.f, 0.f, 0.f, 0.f);
#pragma unroll 4
    for (int s = 0; s < n; s++) {
        float p = __ldg(prob + s);
        float4 x = Xb[(size_t)s * 256];
        acc.x = fmaf(p, x.x, acc.x);
        acc.y = fmaf(p, x.y, acc.y);
        acc.z = fmaf(p, x.z, acc.z);
        acc.w = fmaf(p, x.w, acc.w);
    }
    ((float4*)g_opart)[(b * 16 + sc) * 256 + tid] = acc;
}

__global__ void output_reduce(const int* __restrict__ lengths, float* __restrict__ out) {
    int b = blockIdx.x;
    int tid = threadIdx.x;
    int kmax = min(16, (lengths[b] + 127) >> 7);
    float4 acc = make_float4(0.f, 0.f, 0.f, 0.f);
    for (int c = 0; c < kmax; c++) {
        float4 v = ((const float4*)g_opart)[(b * 16 + c) * 256 + tid];
        acc.x += v.x; acc.y += v.y; acc.z += v.z; acc.w += v.w;
    }
    ((float4*)out)[b * 256 + tid] = acc;
}

// ---------------------------------------------------------------------------
extern "C" void kernel_launch(void* const* d_in, const int* in_sizes, int n_in,
                              void* d_out, int out_size) {
    const float* X   = (const float*)d_in[0];
    const float* x0  = (const float*)d_in[1];
    const float* x1  = (const float*)d_in[2];
    const float* x2  = (const float*)d_in[3];
    const int*   len = (const int*)  d_in[4];
    const float* WhW = (const float*)d_in[5];
    const float* WhB = (const float*)d_in[6];
    const float* W0  = (const float*)d_in[7];
    const float* W1  = (const float*)d_in[8];
    const float* W2  = (const float*)d_in[9];
    const float* V   = (const float*)d_in[10];
    float* out = (float*)d_out;

    static bool attr_done = false;
    if (!attr_done) {
        cudaFuncSetAttribute(scores_mma, cudaFuncAttributeMaxDynamicSharedMemorySize, SMEM_SZ);
        attr_done = true;
    }

    prep_w<<<512, 256>>>(WhW);
    ctx_kernel<<<Bb, 512>>>(x0, x1, x2, W0, W1, W2, WhB);
    scores_mma<<<dim3(32, 2, Bb), 256, SMEM_SZ>>>(X, V, len);
    softmax_kernel<<<Bb, 256>>>(len, out);
    output_partial<<<dim3(16, Bb), 256>>>(X, len, out);
    output_reduce<<<Bb, 256>>>(len, out);
}

// round 12
// speedup vs baseline: 1.1843x; 1.1843x over previous
#include <cuda_runtime.h>
#include <cuda_fp16.h>
#include <math_constants.h>
#include <cstdint>

#define Bb 64
#define Ss 2048
#define Hh 1024
#define Aa 512

// ---------------- device scratch (no allocation allowed) --------------------
__device__ float g_C[Bb * Aa];
__device__ float g_sc0[Bb * Ss];
__device__ float g_sc1[Bb * Ss];
__device__ float g_opart[Bb * 16 * Hh];
__device__ __half g_W16[Aa * Hh];

// ---------------- helpers ---------------------------------------------------
__device__ __forceinline__ uint32_t smem_u32(const void* p) {
    uint32_t a;
    asm("{ .reg .u64 t; cvta.to.shared.u64 t, %1; cvt.u32.u64 %0, t; }" : "=r"(a) : "l"(p));
    return a;
}
__device__ __forceinline__ void cp_async16(uint32_t dst, const void* src) {
    asm volatile("cp.async.cg.shared.global [%0], [%1], 16;" :: "r"(dst), "l"(src) : "memory");
}
__device__ __forceinline__ void cp_commit() {
    asm volatile("cp.async.commit_group;" ::: "memory");
}
__device__ __forceinline__ void cp_wait_all() {
    asm volatile("cp.async.wait_group 0;" ::: "memory");
}
__device__ __forceinline__ void ldmx4(uint32_t& r0, uint32_t& r1, uint32_t& r2, uint32_t& r3,
                                      uint32_t addr) {
    asm volatile("ldmatrix.sync.aligned.m8n8.x4.shared.b16 {%0,%1,%2,%3}, [%4];"
                 : "=r"(r0), "=r"(r1), "=r"(r2), "=r"(r3) : "r"(addr));
}
__device__ __forceinline__ void mma_f16(float* d, const uint32_t* a, const uint32_t* b) {
    asm volatile(
        "mma.sync.aligned.m16n8k16.row.col.f32.f16.f16.f32 "
        "{%0,%1,%2,%3}, {%4,%5,%6,%7}, {%8,%9}, {%0,%1,%2,%3};"
        : "+f"(d[0]), "+f"(d[1]), "+f"(d[2]), "+f"(d[3])
        : "r"(a[0]), "r"(a[1]), "r"(a[2]), "r"(a[3]), "r"(b[0]), "r"(b[1]));
}
__device__ __forceinline__ uint32_t pack_h2(float a, float b) {
    __half2 h = __float22half2_rn(make_float2(a, b));
    return *(uint32_t*)&h;
}

// smem: X triple-buffered (3 slots x 20480: sub0 +0, sub1 +10240),
//       W double-buffered (2 stages x 40960: sub0 +0, sub1 +20480). 80B rows.
#define XSLOT_STRIDE 20480
#define OFF_XB       10240
#define OFF_W0       61440
#define WSTG_STRIDE  40960
#define OFF_WB       20480
#define OFF_SCP      143360          // 512 floats
#define OFF_CS       145408          // 256 floats
#define OFF_VS       146432          // 256 floats
#define SMEM_SZ      147456

// ---------------------------------------------------------------------------
// prep_w: round Wh (fp32 [512][1024]) to fp16, row-major single plane.
// ---------------------------------------------------------------------------
__global__ void prep_w(const float* __restrict__ Wh) {
    int a = blockIdx.x;
    int t = threadIdx.x;
    float4 v = *(const float4*)(Wh + (size_t)a * 1024 + t * 4);
    uint2 w;
    w.x = pack_h2(v.x, v.y);
    w.y = pack_h2(v.z, v.w);
    *(uint2*)(g_W16 + (size_t)a * 1024 + t * 4) = w;
}

// ---------------------------------------------------------------------------
// ctx: C[b,a] = Wh_b[a] + x0@W0[a] + x1@W1[a] + x2@W2[a]
// ---------------------------------------------------------------------------
__global__ void ctx_kernel(const float* __restrict__ x0,
                           const float* __restrict__ x1,
                           const float* __restrict__ x2,
                           const float* __restrict__ W0,
                           const float* __restrict__ W1,
                           const float* __restrict__ W2,
                           const float* __restrict__ Whb) {
    __shared__ float xs[2048];
    int b = blockIdx.x;
    int t = threadIdx.x;
    xs[t]        = x0[b * 1024 + t];
    xs[t + 512]  = x0[b * 1024 + t + 512];
    xs[1024 + t] = x1[b * 512 + t];
    xs[1536 + t] = x2[b * 512 + t];
    __syncthreads();
    int a = t;
    float acc = Whb[a];
    const float4* w0 = (const float4*)(W0 + (size_t)a * 1024);
    const float4* xv = (const float4*)xs;
#pragma unroll 8
    for (int i = 0; i < 256; i++) {
        float4 w = w0[i]; float4 x = xv[i];
        acc += w.x * x.x + w.y * x.y + w.z * x.z + w.w * x.w;
    }
    const float4* w1 = (const float4*)(W1 + (size_t)a * 512);
    const float4* x1v = (const float4*)(xs + 1024);
#pragma unroll 8
    for (int i = 0; i < 128; i++) {
        float4 w = w1[i]; float4 x = x1v[i];
        acc += w.x * x.x + w.y * x.y + w.z * x.z + w.w * x.w;
    }
    const float4* w2 = (const float4*)(W2 + (size_t)a * 512);
    const float4* x2v = (const float4*)(xs + 1536);
#pragma unroll 8
    for (int i = 0; i < 128; i++) {
        float4 w = w2[i]; float4 x = x2v[i];
        acc += w.x * x.x + w.y * x.y + w.z * x.z + w.w * x.w;
    }
    g_C[b * Aa + a] = acc;
}

// ---------------------------------------------------------------------------
// scores_mma: fused scores, fp16 single-pass, BK=64, 16 k-iters,
// ONE barrier per iter: X triple-buffered (STS), W double-buffered (cp.async).
// Order per iter: wait_group(0); bar; issueW(ck+1); storeX(ck+2); loadX(ck+3);
// MMA(ck). grid (16 st, 2 ah, 64 b), 512 threads (16 warps 4x4), warp 32x64.
// ---------------------------------------------------------------------------
__global__ void __launch_bounds__(512)
scores_mma(const float* __restrict__ X,
           const float* __restrict__ V,
           const int* __restrict__ lengths) {
    extern __shared__ char smem[];
    int st = blockIdx.x, ah = blockIdx.y, b = blockIdx.z;
    int len = lengths[b];
    int s0 = st * 128;
    if (s0 >= len) return;

    int tid = threadIdx.x;
    int wid = tid >> 5;
    int lane = tid & 31;
    int wm = wid >> 2;
    int wn = wid & 3;

    float* cs = (float*)(smem + OFF_CS);
    float* vs = (float*)(smem + OFF_VS);
    if (tid < 256) {
        cs[tid] = g_C[b * Aa + ah * 256 + tid];
        vs[tid] = V[ah * 256 + tid];
    }

    uint32_t sbase = smem_u32(smem);

    // ---- X mapping: per sub-chunk 1024 slots of 8B; 2 slots/thread
    int xrow0 = (tid * 2) >> 3;
    int xq0   = (tid * 2) & 7;
    int xrow1 = (tid * 2 + 1) >> 3;
    int xq1   = (tid * 2 + 1) & 7;
    const float* Xb = X + ((size_t)b * Ss + s0) * Hh;

    // ---- W cp.async mapping: per sub-chunk 1024 ops of 16B; 2 ops/thread
    const __half* wsrc[2];
    uint32_t wdst[2];
#pragma unroll
    for (int i = 0; i < 2; i++) {
        int l = tid * 2 + i;
        int row = l >> 2, ch = l & 3;
        wsrc[i] = g_W16 + ((size_t)(ah * 256 + row)) * Hh + ch * 8;
        wdst[i] = row * 80 + ch * 16;
    }

    auto issueW = [&](int ck) {
        uint32_t sg = sbase + OFF_W0 + (uint32_t)(ck & 1) * WSTG_STRIDE;
        int k0 = ck * 64;
#pragma unroll
        for (int i = 0; i < 2; i++) {
            cp_async16(sg + wdst[i], wsrc[i] + k0);
            cp_async16(sg + wdst[i] + OFF_WB, wsrc[i] + k0 + 32);
        }
        cp_commit();
    };
    auto loadX = [&](int ck, float4* v) {
        int k0 = ck * 64;
        v[0] = *(const float4*)(Xb + (size_t)xrow0 * Hh + k0 + xq0 * 4);
        v[1] = *(const float4*)(Xb + (size_t)xrow1 * Hh + k0 + xq1 * 4);
        v[2] = *(const float4*)(Xb + (size_t)xrow0 * Hh + k0 + 32 + xq0 * 4);
        v[3] = *(const float4*)(Xb + (size_t)xrow1 * Hh + k0 + 32 + xq1 * 4);
    };
    auto storeX = [&](int slot, const float4* v) {
        char* sp = smem + slot * XSLOT_STRIDE;
        uint2 p;
        p.x = pack_h2(v[0].x, v[0].y); p.y = pack_h2(v[0].z, v[0].w);
        *(uint2*)(sp + xrow0 * 80 + xq0 * 8) = p;
        p.x = pack_h2(v[1].x, v[1].y); p.y = pack_h2(v[1].z, v[1].w);
        *(uint2*)(sp + xrow1 * 80 + xq1 * 8) = p;
        p.x = pack_h2(v[2].x, v[2].y); p.y = pack_h2(v[2].z, v[2].w);
        *(uint2*)(sp + OFF_XB + xrow0 * 80 + xq0 * 8) = p;
        p.x = pack_h2(v[3].x, v[3].y); p.y = pack_h2(v[3].z, v[3].w);
        *(uint2*)(sp + OFF_XB + xrow1 * 80 + xq1 * 8) = p;
    };

    // ---- ldmatrix lane geometry (80B rows)
    uint32_t t8 = lane >> 3;
    uint32_t l7 = lane & 7;
    uint32_t arow[2], nrow[4];
#pragma unroll
    for (int i = 0; i < 2; i++)
        arow[i] = (wm * 32 + i * 16 + ((t8 & 1) << 3) + l7) * 80;
#pragma unroll
    for (int g = 0; g < 4; g++)
        nrow[g] = (wn * 64 + (g * 2 + (t8 >> 1)) * 8 + l7) * 80;
    uint32_t ka = (t8 >> 1) << 4;
    uint32_t kb_b = (t8 & 1) << 4;

    float acc[2][8][4];
#pragma unroll
    for (int i = 0; i < 2; i++)
#pragma unroll
        for (int j = 0; j < 8; j++)
#pragma unroll
            for (int r = 0; r < 4; r++) acc[i][j][r] = 0.f;

    // ---- prologue: X slots 0,1 filled; pv = X(2); W(0) issued
    float4 pv[4];
    loadX(0, pv);
    storeX(0, pv);
    loadX(1, pv);
    storeX(1, pv);
    loadX(2, pv);
    issueW(0);

    int xr = 0, xw = 2;   // read slot of iter ck; write slot = (ck+2)%3
#pragma unroll 1
    for (int ck = 0; ck < 16; ck++) {
        cp_wait_all();        // own W(ck) arrived (only group in flight)
        __syncthreads();      // publishes all warps' W(ck); frees slot xw & W stage (ck+1)&1

        if (ck + 1 < 16) issueW(ck + 1);
        if (ck + 2 < 16) storeX(xw, pv);
        if (ck + 3 < 16) loadX(ck + 3, pv);

        uint32_t sb_x = sbase + (uint32_t)xr * XSLOT_STRIDE;
        uint32_t sb_w = sbase + OFF_W0 + (uint32_t)(ck & 1) * WSTG_STRIDE;
#pragma unroll
        for (int h = 0; h < 2; h++) {
            uint32_t Ab = sb_x + (uint32_t)h * OFF_XB;
            uint32_t Bbs = sb_w + (uint32_t)h * OFF_WB;
#pragma unroll
            for (int kf = 0; kf < 2; kf++) {
                uint32_t k16 = kf * 32;
                uint32_t bf[8][2];
#pragma unroll
                for (int g = 0; g < 4; g++) {
                    uint32_t r0, r1, r2, r3;
                    ldmx4(r0, r1, r2, r3, Bbs + nrow[g] + k16 + kb_b);
                    bf[2 * g][0] = r0; bf[2 * g][1] = r1;
                    bf[2 * g + 1][0] = r2; bf[2 * g + 1][1] = r3;
                }
                uint32_t a16[2][4];
#pragma unroll
                for (int i = 0; i < 2; i++)
                    ldmx4(a16[i][0], a16[i][1], a16[i][2], a16[i][3], Ab + arow[i] + k16 + ka);
#pragma unroll
                for (int i = 0; i < 2; i++)
#pragma unroll
                    for (int j = 0; j < 8; j++)
                        mma_f16(acc[i][j], a16[i], bf[j]);
            }
        }
        xr = (xr == 2) ? 0 : xr + 1;
        xw = (xw == 2) ? 0 : xw + 1;
    }

    // ---- epilogue: relu(acc + C) dot V, reduce to per-row scores
    float rs[4] = {0.f, 0.f, 0.f, 0.f};
#pragma unroll
    for (int i = 0; i < 2; i++) {
#pragma unroll
        for (int j = 0; j < 8; j++) {
            int c = wn * 64 + j * 8 + (lane & 3) * 2;
            float v0 = vs[c], v1 = vs[c + 1];
            float c0 = cs[c], c1 = cs[c + 1];
            rs[i * 2 + 0] += fmaxf(acc[i][j][0] + c0, 0.f) * v0
                           + fmaxf(acc[i][j][1] + c1, 0.f) * v1;
            rs[i * 2 + 1] += fmaxf(acc[i][j][2] + c0, 0.f) * v0
                           + fmaxf(acc[i][j][3] + c1, 0.f) * v1;
        }
    }
#pragma unroll
    for (int r = 0; r < 4; r++) {
        rs[r] += __shfl_xor_sync(0xffffffffu, rs[r], 1);
        rs[r] += __shfl_xor_sync(0xffffffffu, rs[r], 2);
    }
    float* scp = (float*)(smem + OFF_SCP);
    if ((lane & 3) == 0) {
        int row = wm * 32 + (lane >> 2);
        scp[wn * 128 + row + 0]  = rs[0];
        scp[wn * 128 + row + 8]  = rs[1];
        scp[wn * 128 + row + 16] = rs[2];
        scp[wn * 128 + row + 24] = rs[3];
    }
    __syncthreads();
    if (tid < 128) {
        float v = scp[tid] + scp[128 + tid] + scp[256 + tid] + scp[384 + tid];
        (ah ? g_sc1 : g_sc0)[b * Ss + s0 + tid] = v;
    }
}

// ---------------------------------------------------------------------------
// softmax over s<len of (g_sc0+g_sc1); prob -> out[B*H ...]
// ---------------------------------------------------------------------------
__global__ void softmax_kernel(const int* __restrict__ lengths, float* __restrict__ out) {
    int b = blockIdx.x;
    int len = lengths[b];
    int tid = threadIdx.x;
    const float* a0 = g_sc0 + b * Ss;
    const float* a1 = g_sc1 + b * Ss;
    float* prob = out + Bb * Hh + (size_t)b * Ss;

    __shared__ float red[8];
    __shared__ float s_m, s_sum;

    float m = -CUDART_INF_F;
    for (int s = tid; s < len; s += 256) m = fmaxf(m, a0[s] + a1[s]);
#pragma unroll
    for (int o = 16; o > 0; o >>= 1) m = fmaxf(m, __shfl_xor_sync(~0u, m, o));
    if ((tid & 31) == 0) red[tid >> 5] = m;
    __syncthreads();
    if (tid == 0) {
        float mm = red[0];
#pragma unroll
        for (int i = 1; i < 8; i++) mm = fmaxf(mm, red[i]);
        s_m = mm;
    }
    __syncthreads();
    m = s_m;

    float sum = 0.f;
    for (int s = tid; s < len; s += 256) sum += expf(a0[s] + a1[s] - m);
#pragma unroll
    for (int o = 16; o > 0; o >>= 1) sum += __shfl_xor_sync(~0u, sum, o);
    if ((tid & 31) == 0) red[tid >> 5] = sum;
    __syncthreads();
    if (tid == 0) {
        float ss = 0.f;
#pragma unroll
        for (int i = 0; i < 8; i++) ss += red[i];
        s_sum = ss;
    }
    __syncthreads();
    float inv = 1.f / s_sum;

    for (int s = tid; s < Ss; s += 256)
        prob[s] = (s < len) ? expf(a0[s] + a1[s] - m) * inv : 0.f;
}

// ---------------------------------------------------------------------------
// output pass, two-phase
// ---------------------------------------------------------------------------
__global__ void output_partial(const float* __restrict__ X,
                               const int* __restrict__ lengths,
                               const float* __restrict__ out) {
    int sc = blockIdx.x, b = blockIdx.y;
    int len = lengths[b];
    int s0 = sc * 128;
    if (s0 >= len) return;
    int n = min(128, len - s0);
    int tid = threadIdx.x;
    const float4* Xb = (const float4*)X + ((size_t)(b * Ss + s0)) * 256 + tid;
    const float* prob = out + Bb * Hh + (size_t)b * Ss + s0;
    float4 acc = make_float4(0.f, 0.f, 0.f, 0.f);
#pragma unroll 4
    for (int s = 0; s < n; s++) {
        float p = __ldg(prob + s);
        float4 x = Xb[(size_t)s * 256];
        acc.x = fmaf(p, x.x, acc.x);
        acc.y = fmaf(p, x.y, acc.y);
        acc.z = fmaf(p, x.z, acc.z);
        acc.w = fmaf(p, x.w, acc.w);
    }
    ((float4*)g_opart)[(b * 16 + sc) * 256 + tid] = acc;
}

__global__ void output_reduce(const int* __restrict__ lengths, float* __restrict__ out) {
    int b = blockIdx.x;
    int tid = threadIdx.x;
    int kmax = min(16, (lengths[b] + 127) >> 7);
    float4 acc = make_float4(0.f, 0.f, 0.f, 0.f);
    for (int c = 0; c < kmax; c++) {
        float4 v = ((const float4*)g_opart)[(b * 16 + c) * 256 + tid];
        acc.x += v.x; acc.y += v.y; acc.z += v.z; acc.w += v.w;
    }
    ((float4*)out)[b * 256 + tid] = acc;
}

// ---------------------------------------------------------------------------
extern "C" void kernel_launch(void* const* d_in, const int* in_sizes, int n_in,
                              void* d_out, int out_size) {
    const float* X   = (const float*)d_in[0];
    const float* x0  = (const float*)d_in[1];
    const float* x1  = (const float*)d_in[2];
    const float* x2  = (const float*)d_in[3];
    const int*   len = (const int*)  d_in[4];
    const float* WhW = (const float*)d_in[5];
    const float* WhB = (const float*)d_in[6];
    const float* W0  = (const float*)d_in[7];
    const float* W1  = (const float*)d_in[8];
    const float* W2  = (const float*)d_in[9];
    const float* V   = (const float*)d_in[10];
    float* out = (float*)d_out;

    static bool attr_done = false;
    if (!attr_done) {
        cudaFuncSetAttribute(scores_mma, cudaFuncAttributeMaxDynamicSharedMemorySize, SMEM_SZ);
        attr_done = true;
    }

    prep_w<<<512, 256>>>(WhW);
    ctx_kernel<<<Bb, 512>>>(x0, x1, x2, W0, W1, W2, WhB);
    scores_mma<<<dim3(16, 2, Bb), 512, SMEM_SZ>>>(X, V, len);
    softmax_kernel<<<Bb, 256>>>(len, out);
    output_partial<<<dim3(16, Bb), 256>>>(X, len, out);
    output_reduce<<<Bb, 256>>>(len, out);
}

// round 13
// speedup vs baseline: 1.2090x; 1.0208x over previous
#include <cuda_runtime.h>
#include <cuda_fp16.h>
#include <math_constants.h>
#include <cstdint>

#define Bb 64
#define Ss 2048
#define Hh 1024
#define Aa 512

// ---------------- device scratch (no allocation allowed) --------------------
__device__ float g_C[Bb * Aa];
__device__ float g_sc0[Bb * Ss];
__device__ float g_sc1[Bb * Ss];
__device__ float g_opart[Bb * 16 * Hh];
__device__ __half g_W16[Aa * Hh];

// ---------------- helpers ---------------------------------------------------
__device__ __forceinline__ uint32_t smem_u32(const void* p) {
    uint32_t a;
    asm("{ .reg .u64 t; cvta.to.shared.u64 t, %1; cvt.u32.u64 %0, t; }" : "=r"(a) : "l"(p));
    return a;
}
__device__ __forceinline__ void cp_async16(uint32_t dst, const void* src) {
    asm volatile("cp.async.cg.shared.global [%0], [%1], 16;" :: "r"(dst), "l"(src) : "memory");
}
__device__ __forceinline__ void cp_commit() {
    asm volatile("cp.async.commit_group;" ::: "memory");
}
__device__ __forceinline__ void ldmx4(uint32_t& r0, uint32_t& r1, uint32_t& r2, uint32_t& r3,
                                      uint32_t addr) {
    asm volatile("ldmatrix.sync.aligned.m8n8.x4.shared.b16 {%0,%1,%2,%3}, [%4];"
                 : "=r"(r0), "=r"(r1), "=r"(r2), "=r"(r3) : "r"(addr));
}
__device__ __forceinline__ void mma_f16(float* d, const uint32_t* a, const uint32_t* b) {
    asm volatile(
        "mma.sync.aligned.m16n8k16.row.col.f32.f16.f16.f32 "
        "{%0,%1,%2,%3}, {%4,%5,%6,%7}, {%8,%9}, {%0,%1,%2,%3};"
        : "+f"(d[0]), "+f"(d[1]), "+f"(d[2]), "+f"(d[3])
        : "r"(a[0]), "r"(a[1]), "r"(a[2]), "r"(a[3]), "r"(b[0]), "r"(b[1]));
}
__device__ __forceinline__ uint32_t pack_h2(float a, float b) {
    __half2 h = __float22half2_rn(make_float2(a, b));
    return *(uint32_t*)&h;
}

// smem: 2 stages of [X sub0 10240 | X sub1 10240 | W sub0 20480 | W sub1 20480]
// (80B rows; BK=64 as two 32-wide sub-chunks)
#define STG_SZ   61440
#define OFF_XB   10240
#define OFF_WA   20480
#define OFF_WB   40960
#define OFF_SCP  122880           // 512 floats
#define OFF_CS   124928           // 256 floats
#define OFF_VS   125952           // 256 floats
#define SMEM_SZ  126976

// ---------------------------------------------------------------------------
// prep_w: round Wh (fp32 [512][1024]) to fp16, row-major single plane.
// ---------------------------------------------------------------------------
__global__ void prep_w(const float* __restrict__ Wh) {
    int a = blockIdx.x;
    int t = threadIdx.x;
    float4 v = *(const float4*)(Wh + (size_t)a * 1024 + t * 4);
    uint2 w;
    w.x = pack_h2(v.x, v.y);
    w.y = pack_h2(v.z, v.w);
    *(uint2*)(g_W16 + (size_t)a * 1024 + t * 4) = w;
}

// ---------------------------------------------------------------------------
// ctx: C[b,a] = Wh_b[a] + x0@W0[a] + x1@W1[a] + x2@W2[a]
// ---------------------------------------------------------------------------
__global__ void ctx_kernel(const float* __restrict__ x0,
                           const float* __restrict__ x1,
                           const float* __restrict__ x2,
                           const float* __restrict__ W0,
                           const float* __restrict__ W1,
                           const float* __restrict__ W2,
                           const float* __restrict__ Whb) {
    __shared__ float xs[2048];
    int b = blockIdx.x;
    int t = threadIdx.x;
    xs[t]        = x0[b * 1024 + t];
    xs[t + 512]  = x0[b * 1024 + t + 512];
    xs[1024 + t] = x1[b * 512 + t];
    xs[1536 + t] = x2[b * 512 + t];
    __syncthreads();
    int a = t;
    float acc = Whb[a];
    const float4* w0 = (const float4*)(W0 + (size_t)a * 1024);
    const float4* xv = (const float4*)xs;
#pragma unroll 8
    for (int i = 0; i < 256; i++) {
        float4 w = w0[i]; float4 x = xv[i];
        acc += w.x * x.x + w.y * x.y + w.z * x.z + w.w * x.w;
    }
    const float4* w1 = (const float4*)(W1 + (size_t)a * 512);
    const float4* x1v = (const float4*)(xs + 1024);
#pragma unroll 8
    for (int i = 0; i < 128; i++) {
        float4 w = w1[i]; float4 x = x1v[i];
        acc += w.x * x.x + w.y * x.y + w.z * x.z + w.w * x.w;
    }
    const float4* w2 = (const float4*)(W2 + (size_t)a * 512);
    const float4* x2v = (const float4*)(xs + 1536);
#pragma unroll 8
    for (int i = 0; i < 128; i++) {
        float4 w = w2[i]; float4 x = x2v[i];
        acc += w.x * x.x + w.y * x.y + w.z * x.z + w.w * x.w;
    }
    g_C[b * Aa + a] = acc;
}

// ---------------------------------------------------------------------------
// scores_mma: fused scores, fp16 single-pass, BK=64, 16 k-iters, 2 stages,
// 2 barriers per iter (round-9 champion structure).
// grid (16 st, 2 ah, 64 b), 512 threads (16 warps 4x4), warp 32x64.
// ---------------------------------------------------------------------------
__global__ void __launch_bounds__(512)
scores_mma(const float* __restrict__ X,
           const float* __restrict__ V,
           const int* __restrict__ lengths) {
    extern __shared__ char smem[];
    int st = blockIdx.x, ah = blockIdx.y, b = blockIdx.z;
    int len = lengths[b];
    int s0 = st * 128;
    if (s0 >= len) return;

    int tid = threadIdx.x;
    int wid = tid >> 5;
    int lane = tid & 31;
    int wm = wid >> 2;
    int wn = wid & 3;

    float* cs = (float*)(smem + OFF_CS);
    float* vs = (float*)(smem + OFF_VS);
    if (tid < 256) {
        cs[tid] = g_C[b * Aa + ah * 256 + tid];
        vs[tid] = V[ah * 256 + tid];
    }

    uint32_t sbase = smem_u32(smem);

    // ---- X mapping: per sub-chunk 1024 slots of 8B; 2 slots/thread
    int xrow0 = (tid * 2) >> 3;
    int xq0   = (tid * 2) & 7;
    int xrow1 = (tid * 2 + 1) >> 3;
    int xq1   = (tid * 2 + 1) & 7;
    const float* Xb = X + ((size_t)b * Ss + s0) * Hh;

    // ---- W cp.async mapping: per sub-chunk 1024 ops of 16B; 2 ops/thread
    const __half* wsrc[2];
    uint32_t wdst[2];
#pragma unroll
    for (int i = 0; i < 2; i++) {
        int l = tid * 2 + i;
        int row = l >> 2, ch = l & 3;
        wsrc[i] = g_W16 + ((size_t)(ah * 256 + row)) * Hh + ch * 8;
        wdst[i] = OFF_WA + row * 80 + ch * 16;
    }

    auto issueW = [&](int ck, uint32_t stage_u32) {
        int k0 = ck * 64;
#pragma unroll
        for (int i = 0; i < 2; i++) {
            cp_async16(stage_u32 + wdst[i], wsrc[i] + k0);
            cp_async16(stage_u32 + wdst[i] + (OFF_WB - OFF_WA), wsrc[i] + k0 + 32);
        }
        cp_commit();
    };
    auto loadX = [&](int ck, float4* v) {
        int k0 = ck * 64;
        v[0] = *(const float4*)(Xb + (size_t)xrow0 * Hh + k0 + xq0 * 4);
        v[1] = *(const float4*)(Xb + (size_t)xrow1 * Hh + k0 + xq1 * 4);
        v[2] = *(const float4*)(Xb + (size_t)xrow0 * Hh + k0 + 32 + xq0 * 4);
        v[3] = *(const float4*)(Xb + (size_t)xrow1 * Hh + k0 + 32 + xq1 * 4);
    };
    auto storeX = [&](char* sp, const float4* v) {
        uint2 p;
        p.x = pack_h2(v[0].x, v[0].y); p.y = pack_h2(v[0].z, v[0].w);
        *(uint2*)(sp + xrow0 * 80 + xq0 * 8) = p;
        p.x = pack_h2(v[1].x, v[1].y); p.y = pack_h2(v[1].z, v[1].w);
        *(uint2*)(sp + xrow1 * 80 + xq1 * 8) = p;
        p.x = pack_h2(v[2].x, v[2].y); p.y = pack_h2(v[2].z, v[2].w);
        *(uint2*)(sp + OFF_XB + xrow0 * 80 + xq0 * 8) = p;
        p.x = pack_h2(v[3].x, v[3].y); p.y = pack_h2(v[3].z, v[3].w);
        *(uint2*)(sp + OFF_XB + xrow1 * 80 + xq1 * 8) = p;
    };

    // ---- ldmatrix lane geometry (80B rows)
    uint32_t t8 = lane >> 3;
    uint32_t l7 = lane & 7;
    uint32_t arow[2], nrow[4];
#pragma unroll
    for (int i = 0; i < 2; i++)
        arow[i] = (wm * 32 + i * 16 + ((t8 & 1) << 3) + l7) * 80;
#pragma unroll
    for (int g = 0; g < 4; g++)
        nrow[g] = (wn * 64 + (g * 2 + (t8 >> 1)) * 8 + l7) * 80;
    uint32_t ka = (t8 >> 1) << 4;
    uint32_t kb_b = (t8 & 1) << 4;

    float acc[2][8][4];
#pragma unroll
    for (int i = 0; i < 2; i++)
#pragma unroll
        for (int j = 0; j < 8; j++)
#pragma unroll
            for (int r = 0; r < 4; r++) acc[i][j][r] = 0.f;

    // ---- prologue: fill stages 0,1
    {
        float4 v[4];
        issueW(0, sbase);
        loadX(0, v);
        storeX(smem, v);
        issueW(1, sbase + STG_SZ);
        loadX(1, v);
        storeX(smem + STG_SZ, v);
    }

    // ---- main loop: 16 k-iters of BK=64, 2 barriers each
    float4 pv[4];
#pragma unroll 1
    for (int ck = 0; ck < 16; ck++) {
        // hoisted X prefetch: LDGs fill during the cp.async wait + barrier
        if (ck + 2 <= 15) loadX(ck + 2, pv);

        if (ck == 15) asm volatile("cp.async.wait_group 0;" ::: "memory");
        else          asm volatile("cp.async.wait_group 1;" ::: "memory");
        __syncthreads();

        uint32_t sb = sbase + (uint32_t)(ck & 1) * STG_SZ;
#pragma unroll
        for (int h = 0; h < 2; h++) {
            uint32_t Ab = sb + (uint32_t)h * OFF_XB;
            uint32_t Bbs = sb + OFF_WA + (uint32_t)h * (OFF_WB - OFF_WA);
#pragma unroll
            for (int kf = 0; kf < 2; kf++) {
                uint32_t k16 = kf * 32;
                uint32_t bf[8][2];
#pragma unroll
                for (int g = 0; g < 4; g++) {
                    uint32_t r0, r1, r2, r3;
                    ldmx4(r0, r1, r2, r3, Bbs + nrow[g] + k16 + kb_b);
                    bf[2 * g][0] = r0; bf[2 * g][1] = r1;
                    bf[2 * g + 1][0] = r2; bf[2 * g + 1][1] = r3;
                }
                uint32_t a16[2][4];
#pragma unroll
                for (int i = 0; i < 2; i++)
                    ldmx4(a16[i][0], a16[i][1], a16[i][2], a16[i][3], Ab + arow[i] + k16 + ka);
#pragma unroll
                for (int i = 0; i < 2; i++)
#pragma unroll
                    for (int j = 0; j < 8; j++)
                        mma_f16(acc[i][j], a16[i], bf[j]);
            }
        }
        __syncthreads();

        if (ck + 2 <= 15) {
            // cp.async first: LSU starts the L2 fetch before the STS burst
            issueW(ck + 2, sbase + (uint32_t)(ck & 1) * STG_SZ);
            storeX(smem + (ck & 1) * STG_SZ, pv);
        }
    }

    // ---- epilogue: relu(acc + C) dot V, reduce to per-row scores
    float rs[4] = {0.f, 0.f, 0.f, 0.f};
#pragma unroll
    for (int i = 0; i < 2; i++) {
#pragma unroll
        for (int j = 0; j < 8; j++) {
            int c = wn * 64 + j * 8 + (lane & 3) * 2;
            float v0 = vs[c], v1 = vs[c + 1];
            float c0 = cs[c], c1 = cs[c + 1];
            rs[i * 2 + 0] += fmaxf(acc[i][j][0] + c0, 0.f) * v0
                           + fmaxf(acc[i][j][1] + c1, 0.f) * v1;
            rs[i * 2 + 1] += fmaxf(acc[i][j][2] + c0, 0.f) * v0
                           + fmaxf(acc[i][j][3] + c1, 0.f) * v1;
        }
    }
#pragma unroll
    for (int r = 0; r < 4; r++) {
        rs[r] += __shfl_xor_sync(0xffffffffu, rs[r], 1);
        rs[r] += __shfl_xor_sync(0xffffffffu, rs[r], 2);
    }
    float* scp = (float*)(smem + OFF_SCP);
    if ((lane & 3) == 0) {
        int row = wm * 32 + (lane >> 2);
        scp[wn * 128 + row + 0]  = rs[0];
        scp[wn * 128 + row + 8]  = rs[1];
        scp[wn * 128 + row + 16] = rs[2];
        scp[wn * 128 + row + 24] = rs[3];
    }
    __syncthreads();
    if (tid < 128) {
        float v = scp[tid] + scp[128 + tid] + scp[256 + tid] + scp[384 + tid];
        (ah ? g_sc1 : g_sc0)[b * Ss + s0 + tid] = v;
    }
}

// ---------------------------------------------------------------------------
// softmax over s<len of (g_sc0+g_sc1); prob -> out[B*H ...]
// ---------------------------------------------------------------------------
__global__ void softmax_kernel(const int* __restrict__ lengths, float* __restrict__ out) {
    int b = blockIdx.x;
    int len = lengths[b];
    int tid = threadIdx.x;
    const float* a0 = g_sc0 + b * Ss;
    const float* a1 = g_sc1 + b * Ss;
    float* prob = out + Bb * Hh + (size_t)b * Ss;

    __shared__ float red[8];
    __shared__ float s_m, s_sum;

    float m = -CUDART_INF_F;
    for (int s = tid; s < len; s += 256) m = fmaxf(m, a0[s] + a1[s]);
#pragma unroll
    for (int o = 16; o > 0; o >>= 1) m = fmaxf(m, __shfl_xor_sync(~0u, m, o));
    if ((tid & 31) == 0) red[tid >> 5] = m;
    __syncthreads();
    if (tid == 0) {
        float mm = red[0];
#pragma unroll
        for (int i = 1; i < 8; i++) mm = fmaxf(mm, red[i]);
        s_m = mm;
    }
    __syncthreads();
    m = s_m;

    float sum = 0.f;
    for (int s = tid; s < len; s += 256) sum += expf(a0[s] + a1[s] - m);
#pragma unroll
    for (int o = 16; o > 0; o >>= 1) sum += __shfl_xor_sync(~0u, sum, o);
    if ((tid & 31) == 0) red[tid >> 5] = sum;
    __syncthreads();
    if (tid == 0) {
        float ss = 0.f;
#pragma unroll
        for (int i = 0; i < 8; i++) ss += red[i];
        s_sum = ss;
    }
    __syncthreads();
    float inv = 1.f / s_sum;

    for (int s = tid; s < Ss; s += 256)
        prob[s] = (s < len) ? expf(a0[s] + a1[s] - m) * inv : 0.f;
}

// ---------------------------------------------------------------------------
// output pass, two-phase
// ---------------------------------------------------------------------------
__global__ void output_partial(const float* __restrict__ X,
                               const int* __restrict__ lengths,
                               const float* __restrict__ out) {
    int sc = blockIdx.x, b = blockIdx.y;
    int len = lengths[b];
    int s0 = sc * 128;
    if (s0 >= len) return;
    int n = min(128, len - s0);
    int tid = threadIdx.x;
    const float4* Xb = (const float4*)X + ((size_t)(b * Ss + s0)) * 256 + tid;
    const float* prob = out + Bb * Hh + (size_t)b * Ss + s0;
    float4 acc = make_float4(0.f, 0.f, 0.f, 0.f);
#pragma unroll 4
    for (int s = 0; s < n; s++) {
        float p = __ldg(prob + s);
        float4 x = Xb[(size_t)s * 256];
        acc.x = fmaf(p, x.x, acc.x);
        acc.y = fmaf(p, x.y, acc.y);
        acc.z = fmaf(p, x.z, acc.z);
        acc.w = fmaf(p, x.w, acc.w);
    }
    ((float4*)g_opart)[(b * 16 + sc) * 256 + tid] = acc;
}

__global__ void output_reduce(const int* __restrict__ lengths, float* __restrict__ out) {
    int b = blockIdx.x;
    int tid = threadIdx.x;
    int kmax = min(16, (lengths[b] + 127) >> 7);
    float4 acc = make_float4(0.f, 0.f, 0.f, 0.f);
    for (int c = 0; c < kmax; c++) {
        float4 v = ((const float4*)g_opart)[(b * 16 + c) * 256 + tid];
        acc.x += v.x; acc.y += v.y; acc.z += v.z; acc.w += v.w;
    }
    ((float4*)out)[b * 256 + tid] = acc;
}

// ---------------------------------------------------------------------------
extern "C" void kernel_launch(void* const* d_in, const int* in_sizes, int n_in,
                              void* d_out, int out_size) {
    const float* X   = (const float*)d_in[0];
    const float* x0  = (const float*)d_in[1];
    const float* x1  = (const float*)d_in[2];
    const float* x2  = (const float*)d_in[3];
    const int*   len = (const int*)  d_in[4];
    const float* WhW = (const float*)d_in[5];
    const float* WhB = (const float*)d_in[6];
    const float* W0  = (const float*)d_in[7];
    const float* W1  = (const float*)d_in[8];
    const float* W2  = (const float*)d_in[9];
    const float* V   = (const float*)d_in[10];
    float* out = (float*)d_out;

    static bool attr_done = false;
    if (!attr_done) {
        cudaFuncSetAttribute(scores_mma, cudaFuncAttributeMaxDynamicSharedMemorySize, SMEM_SZ);
        attr_done = true;
    }

    prep_w<<<512, 256>>>(WhW);
    ctx_kernel<<<Bb, 512>>>(x0, x1, x2, W0, W1, W2, WhB);
    scores_mma<<<dim3(16, 2, Bb), 512, SMEM_SZ>>>(X, V, len);
    softmax_kernel<<<Bb, 256>>>(len, out);
    output_partial<<<dim3(16, Bb), 256>>>(X, len, out);
    output_reduce<<<Bb, 256>>>(len, out);
}

// round 15
// speedup vs baseline: 1.2944x; 1.0706x over previous
#include <cuda_runtime.h>
#include <cuda_fp16.h>
#include <math_constants.h>
#include <cstdint>

#define Bb 64
#define Ss 2048
#define Hh 1024
#define Aa 512

// ---------------- device scratch (no allocation allowed) --------------------
__device__ float g_C[Bb * Aa];
__device__ float g_sc0[Bb * Ss];
__device__ float g_sc1[Bb * Ss];
__device__ float g_opart[Bb * 32 * Hh];
__device__ __half g_W16[Aa * Hh];

// ---------------- helpers ---------------------------------------------------
__device__ __forceinline__ uint32_t smem_u32(const void* p) {
    uint32_t a;
    asm("{ .reg .u64 t; cvta.to.shared.u64 t, %1; cvt.u32.u64 %0, t; }" : "=r"(a) : "l"(p));
    return a;
}
__device__ __forceinline__ void cp_async16(uint32_t dst, const void* src) {
    asm volatile("cp.async.cg.shared.global [%0], [%1], 16;" :: "r"(dst), "l"(src) : "memory");
}
__device__ __forceinline__ void cp_commit() {
    asm volatile("cp.async.commit_group;" ::: "memory");
}
__device__ __forceinline__ void ldmx4(uint32_t& r0, uint32_t& r1, uint32_t& r2, uint32_t& r3,
                                      uint32_t addr) {
    asm volatile("ldmatrix.sync.aligned.m8n8.x4.shared.b16 {%0,%1,%2,%3}, [%4];"
                 : "=r"(r0), "=r"(r1), "=r"(r2), "=r"(r3) : "r"(addr));
}
__device__ __forceinline__ void mma_f16(float* d, const uint32_t* a, const uint32_t* b) {
    asm volatile(
        "mma.sync.aligned.m16n8k16.row.col.f32.f16.f16.f32 "
        "{%0,%1,%2,%3}, {%4,%5,%6,%7}, {%8,%9}, {%0,%1,%2,%3};"
        : "+f"(d[0]), "+f"(d[1]), "+f"(d[2]), "+f"(d[3])
        : "r"(a[0]), "r"(a[1]), "r"(a[2]), "r"(a[3]), "r"(b[0]), "r"(b[1]));
}
__device__ __forceinline__ uint32_t pack_h2(float a, float b) {
    __half2 h = __float22half2_rn(make_float2(a, b));
    return *(uint32_t*)&h;
}

// smem: 2 stages of [X sub0 10240 | X sub1 10240 | W sub0 20480 | W sub1 20480]
// (80B rows; BK=64 as two 32-wide sub-chunks)
#define STG_SZ   61440
#define OFF_XB   10240
#define OFF_WA   20480
#define OFF_WB   40960
#define OFF_SCP  122880           // 512 floats
#define OFF_CS   124928           // 256 floats
#define OFF_VS   125952           // 256 floats
#define SMEM_SZ  126976

// ---------------------------------------------------------------------------
// prep_w: round Wh (fp32 [512][1024]) to fp16, row-major single plane.
// ---------------------------------------------------------------------------
__global__ void prep_w(const float* __restrict__ Wh) {
    int a = blockIdx.x;
    int t = threadIdx.x;
    float4 v = *(const float4*)(Wh + (size_t)a * 1024 + t * 4);
    uint2 w;
    w.x = pack_h2(v.x, v.y);
    w.y = pack_h2(v.z, v.w);
    *(uint2*)(g_W16 + (size_t)a * 1024 + t * 4) = w;
}

// ---------------------------------------------------------------------------
// ctx: C[b,a] = Wh_b[a] + x0@W0[a] + x1@W1[a] + x2@W2[a]
// ---------------------------------------------------------------------------
__global__ void ctx_kernel(const float* __restrict__ x0,
                           const float* __restrict__ x1,
                           const float* __restrict__ x2,
                           const float* __restrict__ W0,
                           const float* __restrict__ W1,
                           const float* __restrict__ W2,
                           const float* __restrict__ Whb) {
    __shared__ float xs[2048];
    int b = blockIdx.x;
    int t = threadIdx.x;
    xs[t]        = x0[b * 1024 + t];
    xs[t + 512]  = x0[b * 1024 + t + 512];
    xs[1024 + t] = x1[b * 512 + t];
    xs[1536 + t] = x2[b * 512 + t];
    __syncthreads();
    int a = t;
    float acc = Whb[a];
    const float4* w0 = (const float4*)(W0 + (size_t)a * 1024);
    const float4* xv = (const float4*)xs;
#pragma unroll 8
    for (int i = 0; i < 256; i++) {
        float4 w = w0[i]; float4 x = xv[i];
        acc += w.x * x.x + w.y * x.y + w.z * x.z + w.w * x.w;
    }
    const float4* w1 = (const float4*)(W1 + (size_t)a * 512);
    const float4* x1v = (const float4*)(xs + 1024);
#pragma unroll 8
    for (int i = 0; i < 128; i++) {
        float4 w = w1[i]; float4 x = x1v[i];
        acc += w.x * x.x + w.y * x.y + w.z * x.z + w.w * x.w;
    }
    const float4* w2 = (const float4*)(W2 + (size_t)a * 512);
    const float4* x2v = (const float4*)(xs + 1536);
#pragma unroll 8
    for (int i = 0; i < 128; i++) {
        float4 w = w2[i]; float4 x = x2v[i];
        acc += w.x * x.x + w.y * x.y + w.z * x.z + w.w * x.w;
    }
    g_C[b * Aa + a] = acc;
}

// ---------------------------------------------------------------------------
// scores_mma: fused scores, fp16 single-pass, BK=64 (16 k-iters, 32 barriers).
// grid (16 st, 2 ah, 64 b), 512 threads (16 warps 4x4), warp 32x64.
// (round-9 champion structure, verbatim)
// ---------------------------------------------------------------------------
__global__ void __launch_bounds__(512)
scores_mma(const float* __restrict__ X,
           const float* __restrict__ V,
           const int* __restrict__ lengths) {
    extern __shared__ char smem[];
    int st = blockIdx.x, ah = blockIdx.y, b = blockIdx.z;
    int len = lengths[b];
    int s0 = st * 128;
    if (s0 >= len) return;

    int tid = threadIdx.x;
    int wid = tid >> 5;
    int lane = tid & 31;
    int wm = wid >> 2;
    int wn = wid & 3;

    float* cs = (float*)(smem + OFF_CS);
    float* vs = (float*)(smem + OFF_VS);
    if (tid < 256) {
        cs[tid] = g_C[b * Aa + ah * 256 + tid];
        vs[tid] = V[ah * 256 + tid];
    }

    uint32_t sbase = smem_u32(smem);

    // ---- X mapping: per sub-chunk 1024 slots of 8B; 2 slots/thread
    int xrow0 = (tid * 2) >> 3;
    int xq0   = (tid * 2) & 7;
    int xrow1 = (tid * 2 + 1) >> 3;
    int xq1   = (tid * 2 + 1) & 7;
    const float* Xb = X + ((size_t)b * Ss + s0) * Hh;

    // ---- W cp.async mapping: per sub-chunk 1024 ops of 16B; 2 ops/thread
    const __half* wsrc[2];
    uint32_t wdst[2];
#pragma unroll
    for (int i = 0; i < 2; i++) {
        int l = tid * 2 + i;
        int row = l >> 2, ch = l & 3;
        wsrc[i] = g_W16 + ((size_t)(ah * 256 + row)) * Hh + ch * 8;
        wdst[i] = OFF_WA + row * 80 + ch * 16;
    }

    auto issueW = [&](int ck, uint32_t stage_u32) {
        int k0 = ck * 64;
#pragma unroll
        for (int i = 0; i < 2; i++) {
            cp_async16(stage_u32 + wdst[i], wsrc[i] + k0);
            cp_async16(stage_u32 + wdst[i] + (OFF_WB - OFF_WA), wsrc[i] + k0 + 32);
        }
        cp_commit();
    };
    auto loadX = [&](int ck, float4* v) {
        int k0 = ck * 64;
        v[0] = *(const float4*)(Xb + (size_t)xrow0 * Hh + k0 + xq0 * 4);
        v[1] = *(const float4*)(Xb + (size_t)xrow1 * Hh + k0 + xq1 * 4);
        v[2] = *(const float4*)(Xb + (size_t)xrow0 * Hh + k0 + 32 + xq0 * 4);
        v[3] = *(const float4*)(Xb + (size_t)xrow1 * Hh + k0 + 32 + xq1 * 4);
    };
    auto storeX = [&](char* sp, const float4* v) {
        uint2 p;
        p.x = pack_h2(v[0].x, v[0].y); p.y = pack_h2(v[0].z, v[0].w);
        *(uint2*)(sp + xrow0 * 80 + xq0 * 8) = p;
        p.x = pack_h2(v[1].x, v[1].y); p.y = pack_h2(v[1].z, v[1].w);
        *(uint2*)(sp + xrow1 * 80 + xq1 * 8) = p;
        p.x = pack_h2(v[2].x, v[2].y); p.y = pack_h2(v[2].z, v[2].w);
        *(uint2*)(sp + OFF_XB + xrow0 * 80 + xq0 * 8) = p;
        p.x = pack_h2(v[3].x, v[3].y); p.y = pack_h2(v[3].z, v[3].w);
        *(uint2*)(sp + OFF_XB + xrow1 * 80 + xq1 * 8) = p;
    };

    // ---- ldmatrix lane geometry (80B rows)
    uint32_t t8 = lane >> 3;
    uint32_t l7 = lane & 7;
    uint32_t arow[2], nrow[4];
#pragma unroll
    for (int i = 0; i < 2; i++)
        arow[i] = (wm * 32 + i * 16 + ((t8 & 1) << 3) + l7) * 80;
#pragma unroll
    for (int g = 0; g < 4; g++)
        nrow[g] = (wn * 64 + (g * 2 + (t8 >> 1)) * 8 + l7) * 80;
    uint32_t ka = (t8 >> 1) << 4;
    uint32_t kb_b = (t8 & 1) << 4;

    float acc[2][8][4];
#pragma unroll
    for (int i = 0; i < 2; i++)
#pragma unroll
        for (int j = 0; j < 8; j++)
#pragma unroll
            for (int r = 0; r < 4; r++) acc[i][j][r] = 0.f;

    // ---- prologue: fill stages 0,1
    {
        float4 v[4];
        issueW(0, sbase);
        loadX(0, v);
        storeX(smem, v);
        issueW(1, sbase + STG_SZ);
        loadX(1, v);
        storeX(smem + STG_SZ, v);
    }

    // ---- main loop: 16 k-iters of BK=64, 2 barriers each
    float4 pv[4];
#pragma unroll 1
    for (int ck = 0; ck < 16; ck++) {
        if (ck == 15) asm volatile("cp.async.wait_group 0;" ::: "memory");
        else          asm volatile("cp.async.wait_group 1;" ::: "memory");
        __syncthreads();

        if (ck + 2 <= 15) loadX(ck + 2, pv);

        uint32_t sb = sbase + (uint32_t)(ck & 1) * STG_SZ;
#pragma unroll
        for (int h = 0; h < 2; h++) {
            uint32_t Ab = sb + (uint32_t)h * OFF_XB;
            uint32_t Bbs = sb + OFF_WA + (uint32_t)h * (OFF_WB - OFF_WA);
#pragma unroll
            for (int kf = 0; kf < 2; kf++) {
                uint32_t k16 = kf * 32;
                uint32_t bf[8][2];
#pragma unroll
                for (int g = 0; g < 4; g++) {
                    uint32_t r0, r1, r2, r3;
                    ldmx4(r0, r1, r2, r3, Bbs + nrow[g] + k16 + kb_b);
                    bf[2 * g][0] = r0; bf[2 * g][1] = r1;
                    bf[2 * g + 1][0] = r2; bf[2 * g + 1][1] = r3;
                }
                uint32_t a16[2][4];
#pragma unroll
                for (int i = 0; i < 2; i++)
                    ldmx4(a16[i][0], a16[i][1], a16[i][2], a16[i][3], Ab + arow[i] + k16 + ka);
#pragma unroll
                for (int i = 0; i < 2; i++)
#pragma unroll
                    for (int j = 0; j < 8; j++)
                        mma_f16(acc[i][j], a16[i], bf[j]);
            }
        }
        __syncthreads();

        if (ck + 2 <= 15) {
            storeX(smem + (ck & 1) * STG_SZ, pv);
            issueW(ck + 2, sbase + (uint32_t)(ck & 1) * STG_SZ);
        }
    }

    // ---- epilogue: relu(acc + C) dot V, reduce to per-row scores
    float rs[4] = {0.f, 0.f, 0.f, 0.f};
#pragma unroll
    for (int i = 0; i < 2; i++) {
#pragma unroll
        for (int j = 0; j < 8; j++) {
            int c = wn * 64 + j * 8 + (lane & 3) * 2;
            float v0 = vs[c], v1 = vs[c + 1];
            float c0 = cs[c], c1 = cs[c + 1];
            rs[i * 2 + 0] += fmaxf(acc[i][j][0] + c0, 0.f) * v0
                           + fmaxf(acc[i][j][1] + c1, 0.f) * v1;
            rs[i * 2 + 1] += fmaxf(acc[i][j][2] + c0, 0.f) * v0
                           + fmaxf(acc[i][j][3] + c1, 0.f) * v1;
        }
    }
#pragma unroll
    for (int r = 0; r < 4; r++) {
        rs[r] += __shfl_xor_sync(0xffffffffu, rs[r], 1);
        rs[r] += __shfl_xor_sync(0xffffffffu, rs[r], 2);
    }
    float* scp = (float*)(smem + OFF_SCP);
    if ((lane & 3) == 0) {
        int row = wm * 32 + (lane >> 2);
        scp[wn * 128 + row + 0]  = rs[0];
        scp[wn * 128 + row + 8]  = rs[1];
        scp[wn * 128 + row + 16] = rs[2];
        scp[wn * 128 + row + 24] = rs[3];
    }
    __syncthreads();
    if (tid < 128) {
        float v = scp[tid] + scp[128 + tid] + scp[256 + tid] + scp[384 + tid];
        (ah ? g_sc1 : g_sc0)[b * Ss + s0 + tid] = v;
    }
}

// ---------------------------------------------------------------------------
// softmax over s<len of (g_sc0+g_sc1); prob -> out[B*H ...]
// ---------------------------------------------------------------------------
__global__ void softmax_kernel(const int* __restrict__ lengths, float* __restrict__ out) {
    int b = blockIdx.x;
    int len = lengths[b];
    int tid = threadIdx.x;
    const float* a0 = g_sc0 + b * Ss;
    const float* a1 = g_sc1 + b * Ss;
    float* prob = out + Bb * Hh + (size_t)b * Ss;

    __shared__ float red[8];
    __shared__ float s_m, s_sum;

    float m = -CUDART_INF_F;
    for (int s = tid; s < len; s += 256) m = fmaxf(m, a0[s] + a1[s]);
#pragma unroll
    for (int o = 16; o > 0; o >>= 1) m = fmaxf(m, __shfl_xor_sync(~0u, m, o));
    if ((tid & 31) == 0) red[tid >> 5] = m;
    __syncthreads();
    if (tid == 0) {
        float mm = red[0];
#pragma unroll
        for (int i = 1; i < 8; i++) mm = fmaxf(mm, red[i]);
        s_m = mm;
    }
    __syncthreads();
    m = s_m;

    float sum = 0.f;
    for (int s = tid; s < len; s += 256) sum += expf(a0[s] + a1[s] - m);
#pragma unroll
    for (int o = 16; o > 0; o >>= 1) sum += __shfl_xor_sync(~0u, sum, o);
    if ((tid & 31) == 0) red[tid >> 5] = sum;
    __syncthreads();
    if (tid == 0) {
        float ss = 0.f;
#pragma unroll
        for (int i = 0; i < 8; i++) ss += red[i];
        s_sum = ss;
    }
    __syncthreads();
    float inv = 1.f / s_sum;

    for (int s = tid; s < Ss; s += 256)
        prob[s] = (s < len) ? expf(a0[s] + a1[s] - m) * inv : 0.f;
}

// ---------------------------------------------------------------------------
// output pass, two-phase: 32 s-chunks of 64 for shorter serial chains
// ---------------------------------------------------------------------------
__global__ void output_partial(const float* __restrict__ X,
                               const int* __restrict__ lengths,
                               const float* __restrict__ out) {
    int sc = blockIdx.x, b = blockIdx.y;
    int len = lengths[b];
    int s0 = sc * 64;
    if (s0 >= len) return;
    int n = min(64, len - s0);
    int tid = threadIdx.x;
    const float4* Xb = (const float4*)X + ((size_t)(b * Ss + s0)) * 256 + tid;
    const float* prob = out + Bb * Hh + (size_t)b * Ss + s0;
    float4 acc = make_float4(0.f, 0.f, 0.f, 0.f);
#pragma unroll 4
    for (int s = 0; s < n; s++) {
        float p = __ldg(prob + s);
        float4 x = Xb[(size_t)s * 256];
        acc.x = fmaf(p, x.x, acc.x);
        acc.y = fmaf(p, x.y, acc.y);
        acc.z = fmaf(p, x.z, acc.z);
        acc.w = fmaf(p, x.w, acc.w);
    }
    ((float4*)g_opart)[(b * 32 + sc) * 256 + tid] = acc;
}

__global__ void output_reduce(const int* __restrict__ lengths, float* __restrict__ out) {
    int b = blockIdx.x;
    int tid = threadIdx.x;
    int kmax = min(32, (lengths[b] + 63) >> 6);
    float4 acc = make_float4(0.f, 0.f, 0.f, 0.f);
    for (int c = 0; c < kmax; c++) {
        float4 v = ((const float4*)g_opart)[(b * 32 + c) * 256 + tid];
        acc.x += v.x; acc.y += v.y; acc.z += v.z; acc.w += v.w;
    }
    ((float4*)out)[b * 256 + tid] = acc;
}

// ---------------------------------------------------------------------------
extern "C" void kernel_launch(void* const* d_in, const int* in_sizes, int n_in,
                              void* d_out, int out_size) {
    const float* X   = (const float*)d_in[0];
    const float* x0  = (const float*)d_in[1];
    const float* x1  = (const float*)d_in[2];
    const float* x2  = (const float*)d_in[3];
    const int*   len = (const int*)  d_in[4];
    const float* WhW = (const float*)d_in[5];
    const float* WhB = (const float*)d_in[6];
    const float* W0  = (const float*)d_in[7];
    const float* W1  = (const float*)d_in[8];
    const float* W2  = (const float*)d_in[9];
    const float* V   = (const float*)d_in[10];
    float* out = (float*)d_out;

    static bool attr_done = false;
    if (!attr_done) {
        cudaFuncSetAttribute(scores_mma, cudaFuncAttributeMaxDynamicSharedMemorySize, SMEM_SZ);
        attr_done = true;
    }

    prep_w<<<512, 256>>>(WhW);
    ctx_kernel<<<Bb, 512>>>(x0, x1, x2, W0, W1, W2, WhB);
    scores_mma<<<dim3(16, 2, Bb), 512, SMEM_SZ>>>(X, V, len);
    softmax_kernel<<<Bb, 256>>>(len, out);
    output_partial<<<dim3(32, Bb), 256>>>(X, len, out);
    output_reduce<<<Bb, 256>>>(len, out);
}

// round 17
// speedup vs baseline: 1.4776x; 1.1416x over previous
#include <cuda_runtime.h>
#include <cuda_fp16.h>
#include <math_constants.h>
#include <cstdint>

#define Bb 64
#define Ss 2048
#define Hh 1024
#define Aa 512

// ---------------- device scratch (no allocation allowed) --------------------
__device__ float g_C[Bb * Aa];
__device__ float g_sc0[Bb * Ss];
__device__ float g_sc1[Bb * Ss];
__device__ float g_opart[Bb * 32 * Hh];
__device__ __half g_W16[Aa * Hh];

// ---------------- helpers ---------------------------------------------------
__device__ __forceinline__ uint32_t smem_u32(const void* p) {
    uint32_t a;
    asm("{ .reg .u64 t; cvta.to.shared.u64 t, %1; cvt.u32.u64 %0, t; }" : "=r"(a) : "l"(p));
    return a;
}
__device__ __forceinline__ void cp_async16(uint32_t dst, const void* src) {
    asm volatile("cp.async.cg.shared.global [%0], [%1], 16;" :: "r"(dst), "l"(src) : "memory");
}
__device__ __forceinline__ void cp_commit() {
    asm volatile("cp.async.commit_group;" ::: "memory");
}
__device__ __forceinline__ void ldmx4(uint32_t& r0, uint32_t& r1, uint32_t& r2, uint32_t& r3,
                                      uint32_t addr) {
    asm volatile("ldmatrix.sync.aligned.m8n8.x4.shared.b16 {%0,%1,%2,%3}, [%4];"
                 : "=r"(r0), "=r"(r1), "=r"(r2), "=r"(r3) : "r"(addr));
}
__device__ __forceinline__ void mma_f16(float* d, const uint32_t* a, const uint32_t* b) {
    asm volatile(
        "mma.sync.aligned.m16n8k16.row.col.f32.f16.f16.f32 "
        "{%0,%1,%2,%3}, {%4,%5,%6,%7}, {%8,%9}, {%0,%1,%2,%3};"
        : "+f"(d[0]), "+f"(d[1]), "+f"(d[2]), "+f"(d[3])
        : "r"(a[0]), "r"(a[1]), "r"(a[2]), "r"(a[3]), "r"(b[0]), "r"(b[1]));
}
__device__ __forceinline__ uint32_t pack_h2(float a, float b) {
    __half2 h = __float22half2_rn(make_float2(a, b));
    return *(uint32_t*)&h;
}

// smem: 2 stages of [X sub0 10240 | X sub1 10240 | W sub0 20480 | W sub1 20480]
// (80B rows; BK=64 as two 32-wide sub-chunks)
#define STG_SZ   61440
#define OFF_XB   10240
#define OFF_WA   20480
#define OFF_WB   40960
#define OFF_SCP  122880           // 512 floats
#define OFF_CS   124928           // 256 floats
#define OFF_VS   125952           // 256 floats
#define SMEM_SZ  126976

// ---------------------------------------------------------------------------
// prep_w: round Wh (fp32 [512][1024]) to fp16, row-major single plane.
// ---------------------------------------------------------------------------
__global__ void prep_w(const float* __restrict__ Wh) {
    int a = blockIdx.x;
    int t = threadIdx.x;
    float4 v = *(const float4*)(Wh + (size_t)a * 1024 + t * 4);
    uint2 w;
    w.x = pack_h2(v.x, v.y);
    w.y = pack_h2(v.z, v.w);
    *(uint2*)(g_W16 + (size_t)a * 1024 + t * 4) = w;
}

// ---------------------------------------------------------------------------
// ctx: C[b,a] = Wh_b[a] + x0@W0[a] + x1@W1[a] + x2@W2[a]
// grid (2 a-halves, 32 batch-pairs), 256 threads (one a each, 2 batches).
// Each W element loaded once, used for both batches -> L2 traffic halved.
// ---------------------------------------------------------------------------
__global__ void ctx_kernel(const float* __restrict__ x0,
                           const float* __restrict__ x1,
                           const float* __restrict__ x2,
                           const float* __restrict__ W0,
                           const float* __restrict__ W1,
                           const float* __restrict__ W2,
                           const float* __restrict__ Whb) {
    __shared__ float xs[2][2048];
    int ah = blockIdx.x;
    int bt = blockIdx.y;
    int t = threadIdx.x;
    int b0 = bt * 2;

#pragma unroll
    for (int bb = 0; bb < 2; bb++) {
        int b = b0 + bb;
        for (int i = t; i < 1024; i += 256) xs[bb][i] = x0[b * 1024 + i];
        for (int i = t; i < 512; i += 256) {
            xs[bb][1024 + i] = x1[b * 512 + i];
            xs[bb][1536 + i] = x2[b * 512 + i];
        }
    }
    __syncthreads();

    int a = ah * 256 + t;
    float bias = Whb[a];
    float acc0 = bias, acc1 = bias;

    const float4* w0 = (const float4*)(W0 + (size_t)a * 1024);
    const float4* xv0 = (const float4*)xs[0];
    const float4* xv1 = (const float4*)xs[1];
#pragma unroll 8
    for (int i = 0; i < 256; i++) {
        float4 w = w0[i];
        float4 xa = xv0[i], xb = xv1[i];
        acc0 += w.x * xa.x + w.y * xa.y + w.z * xa.z + w.w * xa.w;
        acc1 += w.x * xb.x + w.y * xb.y + w.z * xb.z + w.w * xb.w;
    }
    const float4* w1 = (const float4*)(W1 + (size_t)a * 512);
    const float4* x1v0 = (const float4*)(xs[0] + 1024);
    const float4* x1v1 = (const float4*)(xs[1] + 1024);
#pragma unroll 8
    for (int i = 0; i < 128; i++) {
        float4 w = w1[i];
        float4 xa = x1v0[i], xb = x1v1[i];
        acc0 += w.x * xa.x + w.y * xa.y + w.z * xa.z + w.w * xa.w;
        acc1 += w.x * xb.x + w.y * xb.y + w.z * xb.z + w.w * xb.w;
    }
    const float4* w2 = (const float4*)(W2 + (size_t)a * 512);
    const float4* x2v0 = (const float4*)(xs[0] + 1536);
    const float4* x2v1 = (const float4*)(xs[1] + 1536);
#pragma unroll 8
    for (int i = 0; i < 128; i++) {
        float4 w = w2[i];
        float4 xa = x2v0[i], xb = x2v1[i];
        acc0 += w.x * xa.x + w.y * xa.y + w.z * xa.z + w.w * xa.w;
        acc1 += w.x * xb.x + w.y * xb.y + w.z * xb.z + w.w * xb.w;
    }
    g_C[(b0 + 0) * Aa + a] = acc0;
    g_C[(b0 + 1) * Aa + a] = acc1;
}

// ---------------------------------------------------------------------------
// scores_mma: fused scores, fp16 single-pass, BK=64 (16 k-iters, 32 barriers).
// grid (16 st, 2 ah, 64 b), 512 threads (16 warps 4x4), warp 32x64.
// (round-9 champion structure, verbatim)
// ---------------------------------------------------------------------------
__global__ void __launch_bounds__(512)
scores_mma(const float* __restrict__ X,
           const float* __restrict__ V,
           const int* __restrict__ lengths) {
    extern __shared__ char smem[];
    int st = blockIdx.x, ah = blockIdx.y, b = blockIdx.z;
    int len = lengths[b];
    int s0 = st * 128;
    if (s0 >= len) return;

    int tid = threadIdx.x;
    int wid = tid >> 5;
    int lane = tid & 31;
    int wm = wid >> 2;
    int wn = wid & 3;

    float* cs = (float*)(smem + OFF_CS);
    float* vs = (float*)(smem + OFF_VS);
    if (tid < 256) {
        cs[tid] = g_C[b * Aa + ah * 256 + tid];
        vs[tid] = V[ah * 256 + tid];
    }

    uint32_t sbase = smem_u32(smem);

    // ---- X mapping: per sub-chunk 1024 slots of 8B; 2 slots/thread
    int xrow0 = (tid * 2) >> 3;
    int xq0   = (tid * 2) & 7;
    int xrow1 = (tid * 2 + 1) >> 3;
    int xq1   = (tid * 2 + 1) & 7;
    const float* Xb = X + ((size_t)b * Ss + s0) * Hh;

    // ---- W cp.async mapping: per sub-chunk 1024 ops of 16B; 2 ops/thread
    const __half* wsrc[2];
    uint32_t wdst[2];
#pragma unroll
    for (int i = 0; i < 2; i++) {
        int l = tid * 2 + i;
        int row = l >> 2, ch = l & 3;
        wsrc[i] = g_W16 + ((size_t)(ah * 256 + row)) * Hh + ch * 8;
        wdst[i] = OFF_WA + row * 80 + ch * 16;
    }

    auto issueW = [&](int ck, uint32_t stage_u32) {
        int k0 = ck * 64;
#pragma unroll
        for (int i = 0; i < 2; i++) {
            cp_async16(stage_u32 + wdst[i], wsrc[i] + k0);
            cp_async16(stage_u32 + wdst[i] + (OFF_WB - OFF_WA), wsrc[i] + k0 + 32);
        }
        cp_commit();
    };
    auto loadX = [&](int ck, float4* v) {
        int k0 = ck * 64;
        v[0] = *(const float4*)(Xb + (size_t)xrow0 * Hh + k0 + xq0 * 4);
        v[1] = *(const float4*)(Xb + (size_t)xrow1 * Hh + k0 + xq1 * 4);
        v[2] = *(const float4*)(Xb + (size_t)xrow0 * Hh + k0 + 32 + xq0 * 4);
        v[3] = *(const float4*)(Xb + (size_t)xrow1 * Hh + k0 + 32 + xq1 * 4);
    };
    auto storeX = [&](char* sp, const float4* v) {
        uint2 p;
        p.x = pack_h2(v[0].x, v[0].y); p.y = pack_h2(v[0].z, v[0].w);
        *(uint2*)(sp + xrow0 * 80 + xq0 * 8) = p;
        p.x = pack_h2(v[1].x, v[1].y); p.y = pack_h2(v[1].z, v[1].w);
        *(uint2*)(sp + xrow1 * 80 + xq1 * 8) = p;
        p.x = pack_h2(v[2].x, v[2].y); p.y = pack_h2(v[2].z, v[2].w);
        *(uint2*)(sp + OFF_XB + xrow0 * 80 + xq0 * 8) = p;
        p.x = pack_h2(v[3].x, v[3].y); p.y = pack_h2(v[3].z, v[3].w);
        *(uint2*)(sp + OFF_XB + xrow1 * 80 + xq1 * 8) = p;
    };

    // ---- ldmatrix lane geometry (80B rows)
    uint32_t t8 = lane >> 3;
    uint32_t l7 = lane & 7;
    uint32_t arow[2], nrow[4];
#pragma unroll
    for (int i = 0; i < 2; i++)
        arow[i] = (wm * 32 + i * 16 + ((t8 & 1) << 3) + l7) * 80;
#pragma unroll
    for (int g = 0; g < 4; g++)
        nrow[g] = (wn * 64 + (g * 2 + (t8 >> 1)) * 8 + l7) * 80;
    uint32_t ka = (t8 >> 1) << 4;
    uint32_t kb_b = (t8 & 1) << 4;

    float acc[2][8][4];
#pragma unroll
    for (int i = 0; i < 2; i++)
#pragma unroll
        for (int j = 0; j < 8; j++)
#pragma unroll
            for (int r = 0; r < 4; r++) acc[i][j][r] = 0.f;

    // ---- prologue: fill stages 0,1
    {
        float4 v[4];
        issueW(0, sbase);
        loadX(0, v);
        storeX(smem, v);
        issueW(1, sbase + STG_SZ);
        loadX(1, v);
        storeX(smem + STG_SZ, v);
    }

    // ---- main loop: 16 k-iters of BK=64, 2 barriers each
    float4 pv[4];
#pragma unroll 1
    for (int ck = 0; ck < 16; ck++) {
        if (ck == 15) asm volatile("cp.async.wait_group 0;" ::: "memory");
        else          asm volatile("cp.async.wait_group 1;" ::: "memory");
        __syncthreads();

        if (ck + 2 <= 15) loadX(ck + 2, pv);

        uint32_t sb = sbase + (uint32_t)(ck & 1) * STG_SZ;
#pragma unroll
        for (int h = 0; h < 2; h++) {
            uint32_t Ab = sb + (uint32_t)h * OFF_XB;
            uint32_t Bbs = sb + OFF_WA + (uint32_t)h * (OFF_WB - OFF_WA);
#pragma unroll
            for (int kf = 0; kf < 2; kf++) {
                uint32_t k16 = kf * 32;
                uint32_t bf[8][2];
#pragma unroll
                for (int g = 0; g < 4; g++) {
                    uint32_t r0, r1, r2, r3;
                    ldmx4(r0, r1, r2, r3, Bbs + nrow[g] + k16 + kb_b);
                    bf[2 * g][0] = r0; bf[2 * g][1] = r1;
                    bf[2 * g + 1][0] = r2; bf[2 * g + 1][1] = r3;
                }
                uint32_t a16[2][4];
#pragma unroll
                for (int i = 0; i < 2; i++)
                    ldmx4(a16[i][0], a16[i][1], a16[i][2], a16[i][3], Ab + arow[i] + k16 + ka);
#pragma unroll
                for (int i = 0; i < 2; i++)
#pragma unroll
                    for (int j = 0; j < 8; j++)
                        mma_f16(acc[i][j], a16[i], bf[j]);
            }
        }
        __syncthreads();

        if (ck + 2 <= 15) {
            storeX(smem + (ck & 1) * STG_SZ, pv);
            issueW(ck + 2, sbase + (uint32_t)(ck & 1) * STG_SZ);
        }
    }

    // ---- epilogue: relu(acc + C) dot V, reduce to per-row scores
    float rs[4] = {0.f, 0.f, 0.f, 0.f};
#pragma unroll
    for (int i = 0; i < 2; i++) {
#pragma unroll
        for (int j = 0; j < 8; j++) {
            int c = wn * 64 + j * 8 + (lane & 3) * 2;
            float v0 = vs[c], v1 = vs[c + 1];
            float c0 = cs[c], c1 = cs[c + 1];
            rs[i * 2 + 0] += fmaxf(acc[i][j][0] + c0, 0.f) * v0
                           + fmaxf(acc[i][j][1] + c1, 0.f) * v1;
            rs[i * 2 + 1] += fmaxf(acc[i][j][2] + c0, 0.f) * v0
                           + fmaxf(acc[i][j][3] + c1, 0.f) * v1;
        }
    }
#pragma unroll
    for (int r = 0; r < 4; r++) {
        rs[r] += __shfl_xor_sync(0xffffffffu, rs[r], 1);
        rs[r] += __shfl_xor_sync(0xffffffffu, rs[r], 2);
    }
    float* scp = (float*)(smem + OFF_SCP);
    if ((lane & 3) == 0) {
        int row = wm * 32 + (lane >> 2);
        scp[wn * 128 + row + 0]  = rs[0];
        scp[wn * 128 + row + 8]  = rs[1];
        scp[wn * 128 + row + 16] = rs[2];
        scp[wn * 128 + row + 24] = rs[3];
    }
    __syncthreads();
    if (tid < 128) {
        float v = scp[tid] + scp[128 + tid] + scp[256 + tid] + scp[384 + tid];
        (ah ? g_sc1 : g_sc0)[b * Ss + s0 + tid] = v;
    }
}

// ---------------------------------------------------------------------------
// softmax over s<len of (g_sc0+g_sc1); prob -> out[B*H ...]
// ---------------------------------------------------------------------------
__global__ void softmax_kernel(const int* __restrict__ lengths, float* __restrict__ out) {
    int b = blockIdx.x;
    int len = lengths[b];
    int tid = threadIdx.x;
    const float* a0 = g_sc0 + b * Ss;
    const float* a1 = g_sc1 + b * Ss;
    float* prob = out + Bb * Hh + (size_t)b * Ss;

    __shared__ float red[8];
    __shared__ float s_m, s_sum;

    float m = -CUDART_INF_F;
    for (int s = tid; s < len; s += 256) m = fmaxf(m, a0[s] + a1[s]);
#pragma unroll
    for (int o = 16; o > 0; o >>= 1) m = fmaxf(m, __shfl_xor_sync(~0u, m, o));
    if ((tid & 31) == 0) red[tid >> 5] = m;
    __syncthreads();
    if (tid == 0) {
        float mm = red[0];
#pragma unroll
        for (int i = 1; i < 8; i++) mm = fmaxf(mm, red[i]);
        s_m = mm;
    }
    __syncthreads();
    m = s_m;

    float sum = 0.f;
    for (int s = tid; s < len; s += 256) sum += expf(a0[s] + a1[s] - m);
#pragma unroll
    for (int o = 16; o > 0; o >>= 1) sum += __shfl_xor_sync(~0u, sum, o);
    if ((tid & 31) == 0) red[tid >> 5] = sum;
    __syncthreads();
    if (tid == 0) {
        float ss = 0.f;
#pragma unroll
        for (int i = 0; i < 8; i++) ss += red[i];
        s_sum = ss;
    }
    __syncthreads();
    float inv = 1.f / s_sum;

    for (int s = tid; s < Ss; s += 256)
        prob[s] = (s < len) ? expf(a0[s] + a1[s] - m) * inv : 0.f;
}

// ---------------------------------------------------------------------------
// output pass, two-phase: 32 s-chunks of 64 for shorter serial chains
// ---------------------------------------------------------------------------
__global__ void output_partial(const float* __restrict__ X,
                               const int* __restrict__ lengths,
                               const float* __restrict__ out) {
    int sc = blockIdx.x, b = blockIdx.y;
    int len = lengths[b];
    int s0 = sc * 64;
    if (s0 >= len) return;
    int n = min(64, len - s0);
    int tid = threadIdx.x;
    const float4* Xb = (const float4*)X + ((size_t)(b * Ss + s0)) * 256 + tid;
    const float* prob = out + Bb * Hh + (size_t)b * Ss + s0;
    float4 acc = make_float4(0.f, 0.f, 0.f, 0.f);
#pragma unroll 4
    for (int s = 0; s < n; s++) {
        float p = __ldg(prob + s);
        float4 x = Xb[(size_t)s * 256];
        acc.x = fmaf(p, x.x, acc.x);
        acc.y = fmaf(p, x.y, acc.y);
        acc.z = fmaf(p, x.z, acc.z);
        acc.w = fmaf(p, x.w, acc.w);
    }
    ((float4*)g_opart)[(b * 32 + sc) * 256 + tid] = acc;
}

__global__ void output_reduce(const int* __restrict__ lengths, float* __restrict__ out) {
    int b = blockIdx.x;
    int tid = threadIdx.x;
    int kmax = min(32, (lengths[b] + 63) >> 6);
    float4 acc = make_float4(0.f, 0.f, 0.f, 0.f);
    for (int c = 0; c < kmax; c++) {
        float4 v = ((const float4*)g_opart)[(b * 32 + c) * 256 + tid];
        acc.x += v.x; acc.y += v.y; acc.z += v.z; acc.w += v.w;
    }
    ((float4*)out)[b * 256 + tid] = acc;
}

// ---------------------------------------------------------------------------
extern "C" void kernel_launch(void* const* d_in, const int* in_sizes, int n_in,
                              void* d_out, int out_size) {
    const float* X   = (const float*)d_in[0];
    const float* x0  = (const float*)d_in[1];
    const float* x1  = (const float*)d_in[2];
    const float* x2  = (const float*)d_in[3];
    const int*   len = (const int*)  d_in[4];
    const float* WhW = (const float*)d_in[5];
    const float* WhB = (const float*)d_in[6];
    const float* W0  = (const float*)d_in[7];
    const float* W1  = (const float*)d_in[8];
    const float* W2  = (const float*)d_in[9];
    const float* V   = (const float*)d_in[10];
    float* out = (float*)d_out;

    static bool attr_done = false;
    if (!attr_done) {
        cudaFuncSetAttribute(scores_mma, cudaFuncAttributeMaxDynamicSharedMemorySize, SMEM_SZ);
        attr_done = true;
    }

    prep_w<<<512, 256>>>(WhW);
    ctx_kernel<<<dim3(2, 32), 256>>>(x0, x1, x2, W0, W1, W2, WhB);
    scores_mma<<<dim3(16, 2, Bb), 512, SMEM_SZ>>>(X, V, len);
    softmax_kernel<<<Bb, 256>>>(len, out);
    output_partial<<<dim3(32, Bb), 256>>>(X, len, out);
    output_reduce<<<Bb, 256>>>(len, out);
}